// round 15
// baseline (speedup 1.0000x reference)
#include <cuda_runtime.h>
#include <cuda_fp16.h>
#include <stdint.h>
#include <math.h>

#define B_DIM 2
#define S_DIM 2048
#define M_DIM 1024
#define NHEAD 16
#define HDIM 64
#define FFN_H 2048
#define TOK (B_DIM * S_DIM)          // 4096
#define QKV_N (3 * M_DIM)            // 3072
#define NEGV -1e9f

// ------------------------- scratch (static device) -------------------------
__device__ __half g_xh[TOK * M_DIM];
__device__ __half g_Wqkvh[QKV_N * M_DIM];
__device__ __half g_Woh[M_DIM * M_DIM];
__device__ __half g_W1h[FFN_H * M_DIM];
__device__ __half g_W2h[M_DIM * FFN_H];
__device__ float  g_bqkv[QKV_N];
__device__ __half g_qkvh[TOK * QKV_N];
__device__ __half g_vTh[B_DIM * M_DIM * S_DIM];
__device__ __half g_ctxh[TOK * M_DIM];
__device__ float  g_attnproj[TOK * M_DIM];
__device__ float  g_y[TOK * M_DIM];
__device__ __half g_yh[TOK * M_DIM];
__device__ __half g_ffhh[TOK * FFN_H];
__device__ float  g_ffo[TOK * M_DIM];

// ------------------------- helpers ------------------------------------
__device__ __forceinline__ void mma16(float* c, const unsigned* a, const unsigned* b) {
    asm volatile(
        "mma.sync.aligned.m16n8k16.row.col.f32.f16.f16.f32 "
        "{%0,%1,%2,%3},{%4,%5,%6,%7},{%8,%9},{%0,%1,%2,%3};"
        : "+f"(c[0]), "+f"(c[1]), "+f"(c[2]), "+f"(c[3])
        : "r"(a[0]), "r"(a[1]), "r"(a[2]), "r"(a[3]), "r"(b[0]), "r"(b[1]));
}
__device__ __forceinline__ void ldsm4(unsigned& r0, unsigned& r1, unsigned& r2,
                                      unsigned& r3, uint32_t addr) {
    asm volatile("ldmatrix.sync.aligned.m8n8.x4.shared.b16 {%0,%1,%2,%3}, [%4];"
                 : "=r"(r0), "=r"(r1), "=r"(r2), "=r"(r3) : "r"(addr));
}
__device__ __forceinline__ void cp16(uint32_t dst, const void* src) {
    asm volatile("cp.async.cg.shared.global [%0], [%1], 16;\n" :: "r"(dst), "l"(src));
}
#define CP_COMMIT() asm volatile("cp.async.commit_group;\n" ::: "memory")
#define CP_WAIT(n)  asm volatile("cp.async.wait_group %0;\n" :: "n"(n) : "memory")
__device__ __forceinline__ unsigned h2u(__half2 h) { return *(unsigned*)&h; }

// ------------------------- pack kernels -------------------------------------
__global__ void pack_xh(const float* __restrict__ x) {
    int i = (blockIdx.x * blockDim.x + threadIdx.x) * 4;
    float4 v = *(const float4*)&x[i];
    __half2* d = (__half2*)&g_xh[i];
    d[0] = __floats2half2_rn(v.x, v.y);
    d[1] = __floats2half2_rn(v.z, v.w);
}
__global__ void pack_bias(const float* __restrict__ bq, const float* __restrict__ bk,
                          const float* __restrict__ bv) {
    int idx = blockIdx.x * blockDim.x + threadIdx.x;
    if (idx < QKV_N) {
        int which = idx / M_DIM, hd = idx % M_DIM;
        const float* bb = (which == 0) ? bq : (which == 1) ? bk : bv;
        g_bqkv[idx] = bb[hd];
    }
}
__global__ void pack_qkvT(const float* __restrict__ Wq, const float* __restrict__ Wk,
                          const float* __restrict__ Wv) {
    __shared__ float t[32][33];
    const int k0 = blockIdx.x * 32, n0 = blockIdx.y * 32;
    const int which = n0 >> 10, hd0 = n0 & 1023, h = hd0 >> 6, d0 = hd0 & 63;
    const float* W = (which == 0) ? Wq : (which == 1) ? Wk : Wv;
    const int tx = threadIdx.x, ty = threadIdx.y;
#pragma unroll
    for (int yy = ty; yy < 32; yy += 8)
        t[yy][tx] = W[((size_t)(h << 10) + k0 + yy) * 64 + d0 + tx];
    __syncthreads();
#pragma unroll
    for (int yy = ty; yy < 32; yy += 8)
        g_Wqkvh[(size_t)(n0 + yy) * M_DIM + k0 + tx] = __float2half_rn(t[tx][yy]);
}
__global__ void packT(const float* __restrict__ src, __half* __restrict__ dst,
                      int K, int N) {
    __shared__ float t[32][33];
    const int k0 = blockIdx.x * 32, n0 = blockIdx.y * 32;
    const int tx = threadIdx.x, ty = threadIdx.y;
#pragma unroll
    for (int yy = ty; yy < 32; yy += 8)
        t[yy][tx] = src[(size_t)(k0 + yy) * N + n0 + tx];
    __syncthreads();
#pragma unroll
    for (int yy = ty; yy < 32; yy += 8)
        dst[(size_t)(n0 + yy) * K + k0 + tx] = __float2half_rn(t[tx][yy]);
}

// ------------------------- fp16 tensor-core GEMM (cp.async + ldmatrix) -----
// C = A[M,K] @ Bt[N,K]^T + bias, fp32 accum. Optional ReLU.
// Fragments loaded via ldmatrix.x4: A 4/kstep, B 2/kstep.
template <bool RELU, bool WF, bool WH, bool VT>
__global__ __launch_bounds__(256, 2)
void gemm_h(const __half* __restrict__ A, const __half* __restrict__ Bt,
            const float* __restrict__ bias, float* __restrict__ Cf,
            __half* __restrict__ Ch, __half* __restrict__ vT,
            int M, int N, int K) {
    extern __shared__ unsigned smw[];
    const int tid = threadIdx.x, lane = tid & 31, w = tid >> 5;
    const int wm = w >> 2, wn = w & 3;
    const int g = lane >> 2, tg = lane & 3;
    const int jj = lane >> 3, rr = lane & 7;
    const int row0 = blockIdx.y * 128, col0 = blockIdx.x * 128;

    const int r = tid >> 1, sel = tid & 1;
    const __half* Agp = A + (size_t)(row0 + r) * K + sel * 8;
    const __half* Bgp = Bt + (size_t)(col0 + r) * K + sel * 8;

    uint32_t smA = (uint32_t)__cvta_generic_to_shared(smw);
    uint32_t smB = smA + 4 * 1536 * 4;
    const uint32_t dA = smA + (r * 12 + sel * 4) * 4;
    const uint32_t dB = smB + (r * 12 + sel * 4) * 4;

    // ldmatrix per-lane base addresses
    const uint32_t aLd = smA + (((wm * 64 + (jj & 1) * 8 + rr) * 12) + (jj >> 1) * 4) * 4;
    const uint32_t bLd = smB + (((wn * 32 + (jj >> 1) * 8 + rr) * 12) + (jj & 1) * 4) * 4;

    float acc[4][4][4];
#pragma unroll
    for (int i = 0; i < 4; i++)
#pragma unroll
        for (int j = 0; j < 4; j++)
#pragma unroll
            for (int q = 0; q < 4; q++) acc[i][j][q] = 0.f;

    const int T = K >> 4;

    auto issue = [&](int s, int k0) {
        cp16(dA + s * 6144, Agp + k0);
        cp16(dB + s * 6144, Bgp + k0);
        CP_COMMIT();
    };

    issue(0, 0);
    issue(1, 16);
    issue(2, 32);

    for (int t = 0; t < T; t++) {
        CP_WAIT(2);
        __syncthreads();

        const uint32_t so = (t & 3) * 6144;
        unsigned af[4][4];
#pragma unroll
        for (int mi = 0; mi < 4; mi++)
            ldsm4(af[mi][0], af[mi][1], af[mi][2], af[mi][3], aLd + so + mi * 768);
#pragma unroll
        for (int p = 0; p < 2; p++) {
            unsigned bb[4];
            ldsm4(bb[0], bb[1], bb[2], bb[3], bLd + so + p * 768);
#pragma unroll
            for (int q = 0; q < 2; q++) {
                const int ni = p * 2 + q;
#pragma unroll
                for (int mi = 0; mi < 4; mi++) mma16(acc[mi][ni], af[mi], &bb[2 * q]);
            }
        }

        if (t + 3 < T) issue((t + 3) & 3, (t + 3) * 16);
        else           CP_COMMIT();
    }

    // epilogue
#pragma unroll
    for (int mi = 0; mi < 4; mi++) {
        const int rw = row0 + wm * 64 + mi * 16 + g;
#pragma unroll
        for (int ni = 0; ni < 4; ni++) {
            const int c = col0 + wn * 32 + ni * 8 + 2 * tg;
            const float b0 = bias[c], b1 = bias[c + 1];
            float v0 = acc[mi][ni][0] + b0, v1 = acc[mi][ni][1] + b1;
            float v2 = acc[mi][ni][2] + b0, v3 = acc[mi][ni][3] + b1;
            if (RELU) {
                v0 = fmaxf(v0, 0.f); v1 = fmaxf(v1, 0.f);
                v2 = fmaxf(v2, 0.f); v3 = fmaxf(v3, 0.f);
            }
            if (WF) {
                *(float2*)&Cf[(size_t)rw * N + c] = make_float2(v0, v1);
                *(float2*)&Cf[(size_t)(rw + 8) * N + c] = make_float2(v2, v3);
            }
            if (WH) {
                *(__half2*)&Ch[(size_t)rw * N + c] = __floats2half2_rn(v0, v1);
                *(__half2*)&Ch[(size_t)(rw + 8) * N + c] = __floats2half2_rn(v2, v3);
            }
            if (VT) {
                if (c >= 2 * M_DIM) {
                    const int bb2 = rw >> 11, ss = rw & 2047;
                    const int hd = c - 2 * M_DIM;
                    __half* p0 = vT + (size_t)(bb2 * M_DIM + hd) * S_DIM + ss;
                    p0[0] = __float2half_rn(v0);
                    p0[8] = __float2half_rn(v2);
                    p0[S_DIM]     = __float2half_rn(v1);
                    p0[S_DIM + 8] = __float2half_rn(v3);
                }
            }
        }
    }
}

// ------------------------- fp16 flash attention (ldmatrix) -----------------
__global__ __launch_bounds__(256, 2)
void attn_h(const __half* __restrict__ qkvh, const __half* __restrict__ vTh,
            const int* __restrict__ mask, __half* __restrict__ ctx) {
    extern __shared__ unsigned smu[];
    float* Msf = (float*)(smu + 3 * 4608);      // [3][64]

    const int tid = threadIdx.x, lane = tid & 31, w = tid >> 5;
    const int g = lane >> 2, tg = lane & 3;
    const int jj = lane >> 3, rr = lane & 7;
    const int bh = blockIdx.y, b = bh >> 4, h = bh & 15;
    const int qw = blockIdx.x * 128 + w * 16;

    uint32_t smb = (uint32_t)__cvta_generic_to_shared(smu);
    // ldmatrix base: row rr, fk-offset (jj>>1)*8 words, chunk (jj&1)*4 words
    const uint32_t kLd = smb + (rr * 36 + (jj >> 1) * 8 + (jj & 1) * 4) * 4;
    const uint32_t vLd = kLd + 2304 * 4;

    // Q fragments, pre-scaled by 0.125
    unsigned qf[4][4];
    {
        const __half2 sc = __float2half2_rn(0.125f);
        const __half* qb = qkvh + (size_t)(b * S_DIM + qw + g) * QKV_N + h * HDIM;
        const __half* qb8 = qb + (size_t)8 * QKV_N;
#pragma unroll
        for (int fk = 0; fk < 4; fk++) {
            qf[fk][0] = h2u(__hmul2(*(const __half2*)&qb [fk * 16 + 2 * tg], sc));
            qf[fk][1] = h2u(__hmul2(*(const __half2*)&qb8[fk * 16 + 2 * tg], sc));
            qf[fk][2] = h2u(__hmul2(*(const __half2*)&qb [fk * 16 + 8 + 2 * tg], sc));
            qf[fk][3] = h2u(__hmul2(*(const __half2*)&qb8[fk * 16 + 8 + 2 * tg], sc));
        }
    }

    float of[8][4];
#pragma unroll
    for (int i = 0; i < 8; i++) { of[i][0] = of[i][1] = of[i][2] = of[i][3] = 0.f; }
    float m0 = -INFINITY, m1 = -INFINITY, l0 = 0.f, l1 = 0.f;

    const int key = tid >> 2, c0 = tid & 3;
    auto issue = [&](int s, int kt) {
        const __half* srcK = qkvh + (size_t)(b * S_DIM + kt + key) * QKV_N + M_DIM + h * HDIM;
        const __half* srcV = vTh + (size_t)(b * M_DIM + h * HDIM + key) * S_DIM + kt;
        const uint32_t dK = smb + (s * 4608 + key * 36) * 4;
        const uint32_t dV = dK + 2304 * 4;
#pragma unroll
        for (int i = 0; i < 2; i++) {
            const int c = c0 + i * 4;
            cp16(dK + c * 16, srcK + c * 8);
            cp16(dV + c * 16, srcV + c * 8);
        }
        CP_COMMIT();
        if (tid < 64) Msf[s * 64 + tid] = mask[b * S_DIM + kt + tid] ? 0.f : NEGV;
    };

    const int T = S_DIM / 64;
    issue(0, 0);
    issue(1, 64);

    for (int t = 0; t < T; t++) {
        CP_WAIT(1);
        __syncthreads();

        const int cur = t % 3;
        const uint32_t so = cur * 18432;
        const float* Ms = Msf + cur * 64;

        // S = Q * K^T  (16 x 64 per warp)
        float s[8][4];
#pragma unroll
        for (int fn = 0; fn < 8; fn++) { s[fn][0] = s[fn][1] = s[fn][2] = s[fn][3] = 0.f; }
#pragma unroll
        for (int fn = 0; fn < 8; fn++) {
            unsigned kk[4];
            ldsm4(kk[0], kk[1], kk[2], kk[3], kLd + so + fn * 1152);
            mma16(s[fn], qf[0], &kk[0]);
            mma16(s[fn], qf[1], &kk[2]);
            ldsm4(kk[0], kk[1], kk[2], kk[3], kLd + so + fn * 1152 + 64);
            mma16(s[fn], qf[2], &kk[0]);
            mma16(s[fn], qf[3], &kk[2]);
        }

        // mask + online softmax (rows g, g+8)
        float mx0 = -INFINITY, mx1 = -INFINITY;
#pragma unroll
        for (int fn = 0; fn < 8; fn++) {
            const float mk0 = Ms[fn * 8 + 2 * tg], mk1 = Ms[fn * 8 + 2 * tg + 1];
            s[fn][0] += mk0; s[fn][1] += mk1;
            s[fn][2] += mk0; s[fn][3] += mk1;
            mx0 = fmaxf(mx0, fmaxf(s[fn][0], s[fn][1]));
            mx1 = fmaxf(mx1, fmaxf(s[fn][2], s[fn][3]));
        }
        mx0 = fmaxf(mx0, __shfl_xor_sync(0xffffffffu, mx0, 1));
        mx0 = fmaxf(mx0, __shfl_xor_sync(0xffffffffu, mx0, 2));
        mx1 = fmaxf(mx1, __shfl_xor_sync(0xffffffffu, mx1, 1));
        mx1 = fmaxf(mx1, __shfl_xor_sync(0xffffffffu, mx1, 2));
        const float nm0 = fmaxf(m0, mx0), nm1 = fmaxf(m1, mx1);
        const float a0 = __expf(m0 - nm0), a1 = __expf(m1 - nm1);
        m0 = nm0; m1 = nm1;
        l0 *= a0; l1 *= a1;
#pragma unroll
        for (int fn = 0; fn < 8; fn++) {
            of[fn][0] *= a0; of[fn][1] *= a0;
            of[fn][2] *= a1; of[fn][3] *= a1;
            s[fn][0] = __expf(s[fn][0] - m0);
            s[fn][1] = __expf(s[fn][1] - m0);
            s[fn][2] = __expf(s[fn][2] - m1);
            s[fn][3] = __expf(s[fn][3] - m1);
            l0 += s[fn][0] + s[fn][1];
            l1 += s[fn][2] + s[fn][3];
        }

        // P fragments directly from registers
        unsigned pf[4][4];
#pragma unroll
        for (int j = 0; j < 4; j++) {
            pf[j][0] = h2u(__floats2half2_rn(s[2 * j][0],     s[2 * j][1]));
            pf[j][1] = h2u(__floats2half2_rn(s[2 * j][2],     s[2 * j][3]));
            pf[j][2] = h2u(__floats2half2_rn(s[2 * j + 1][0], s[2 * j + 1][1]));
            pf[j][3] = h2u(__floats2half2_rn(s[2 * j + 1][2], s[2 * j + 1][3]));
        }

        // O += P * V  (V^T via ldmatrix)
#pragma unroll
        for (int fn = 0; fn < 8; fn++) {
            unsigned vv[4];
            ldsm4(vv[0], vv[1], vv[2], vv[3], vLd + so + fn * 1152);
            mma16(of[fn], pf[0], &vv[0]);
            mma16(of[fn], pf[1], &vv[2]);
            ldsm4(vv[0], vv[1], vv[2], vv[3], vLd + so + fn * 1152 + 64);
            mma16(of[fn], pf[2], &vv[0]);
            mma16(of[fn], pf[3], &vv[2]);
        }

        if (t + 2 < T) issue((t + 2) % 3, (t + 2) * 64);
        else           CP_COMMIT();
    }

    l0 += __shfl_xor_sync(0xffffffffu, l0, 1);
    l0 += __shfl_xor_sync(0xffffffffu, l0, 2);
    l1 += __shfl_xor_sync(0xffffffffu, l1, 1);
    l1 += __shfl_xor_sync(0xffffffffu, l1, 2);

    const float i0 = 1.f / fmaxf(l0, 1e-30f), i1 = 1.f / fmaxf(l1, 1e-30f);
    __half* cb = ctx + (size_t)(b * S_DIM + qw) * M_DIM + h * HDIM;
#pragma unroll
    for (int fn = 0; fn < 8; fn++) {
        *(__half2*)&cb[(size_t)g * M_DIM + fn * 8 + 2 * tg] =
            __floats2half2_rn(of[fn][0] * i0, of[fn][1] * i0);
        *(__half2*)&cb[(size_t)(g + 8) * M_DIM + fn * 8 + 2 * tg] =
            __floats2half2_rn(of[fn][2] * i1, of[fn][3] * i1);
    }
}

// ------------------------- residual + layernorm ----------------------------
template <bool WH>
__global__ __launch_bounds__(256)
void ln_kernel(const float* __restrict__ A, const float* __restrict__ R,
               const float* __restrict__ g, const float* __restrict__ be,
               float* __restrict__ out, __half* __restrict__ outh) {
    __shared__ float red[8];
    __shared__ float bcast;
    const int row = blockIdx.x;
    const int tid = threadIdx.x;

    float4 a = ((const float4*)(A + (size_t)row * M_DIM))[tid];
    float4 r = ((const float4*)(R + (size_t)row * M_DIM))[tid];
    float v0 = a.x + r.x, v1 = a.y + r.y, v2 = a.z + r.z, v3 = a.w + r.w;

    float s = v0 + v1 + v2 + v3;
#pragma unroll
    for (int off = 16; off; off >>= 1) s += __shfl_xor_sync(0xffffffffu, s, off);
    if ((tid & 31) == 0) red[tid >> 5] = s;
    __syncthreads();
    if (tid == 0) {
        float t = 0.f;
#pragma unroll
        for (int i = 0; i < 8; i++) t += red[i];
        bcast = t * (1.f / M_DIM);
    }
    __syncthreads();
    const float mu = bcast;

    float d0 = v0 - mu, d1 = v1 - mu, d2 = v2 - mu, d3 = v3 - mu;
    float s2 = d0 * d0 + d1 * d1 + d2 * d2 + d3 * d3;
#pragma unroll
    for (int off = 16; off; off >>= 1) s2 += __shfl_xor_sync(0xffffffffu, s2, off);
    __syncthreads();
    if ((tid & 31) == 0) red[tid >> 5] = s2;
    __syncthreads();
    if (tid == 0) {
        float t = 0.f;
#pragma unroll
        for (int i = 0; i < 8; i++) t += red[i];
        bcast = rsqrtf(t * (1.f / M_DIM) + 1e-5f);
    }
    __syncthreads();
    const float rstd = bcast;

    float4 gg = ((const float4*)g)[tid];
    float4 bb = ((const float4*)be)[tid];
    float4 o;
    o.x = d0 * rstd * gg.x + bb.x;
    o.y = d1 * rstd * gg.y + bb.y;
    o.z = d2 * rstd * gg.z + bb.z;
    o.w = d3 * rstd * gg.w + bb.w;
    ((float4*)(out + (size_t)row * M_DIM))[tid] = o;
    if (WH) {
        __half2* hd = (__half2*)&outh[(size_t)row * M_DIM + tid * 4];
        hd[0] = __floats2half2_rn(o.x, o.y);
        hd[1] = __floats2half2_rn(o.z, o.w);
    }
}

// ---------------------------------------------------------------------------
extern "C" void kernel_launch(void* const* d_in, const int* in_sizes, int n_in,
                              void* d_out, int out_size) {
    const float* x     = (const float*)d_in[0];
    const int*   amask = (const int*)  d_in[1];
    const float* Wq    = (const float*)d_in[2];
    const float* bq    = (const float*)d_in[3];
    const float* Wk    = (const float*)d_in[4];
    const float* bk    = (const float*)d_in[5];
    const float* Wv    = (const float*)d_in[6];
    const float* bv    = (const float*)d_in[7];
    const float* Wo    = (const float*)d_in[8];
    const float* bo    = (const float*)d_in[9];
    const float* g1    = (const float*)d_in[10];
    const float* b1    = (const float*)d_in[11];
    const float* W1    = (const float*)d_in[12];
    const float* bias1 = (const float*)d_in[13];
    const float* W2    = (const float*)d_in[14];
    const float* bias2 = (const float*)d_in[15];
    const float* g2    = (const float*)d_in[16];
    const float* b2    = (const float*)d_in[17];
    float* out = (float*)d_out;

    __half *xh, *Wqkvh, *Woh, *W1h, *W2h, *qkvh, *vTh, *ctxh, *yh, *ffhh;
    float *bqkv, *attnproj, *y, *ffo;
    cudaGetSymbolAddress((void**)&xh,       g_xh);
    cudaGetSymbolAddress((void**)&Wqkvh,    g_Wqkvh);
    cudaGetSymbolAddress((void**)&Woh,      g_Woh);
    cudaGetSymbolAddress((void**)&W1h,      g_W1h);
    cudaGetSymbolAddress((void**)&W2h,      g_W2h);
    cudaGetSymbolAddress((void**)&bqkv,     g_bqkv);
    cudaGetSymbolAddress((void**)&qkvh,     g_qkvh);
    cudaGetSymbolAddress((void**)&vTh,      g_vTh);
    cudaGetSymbolAddress((void**)&ctxh,     g_ctxh);
    cudaGetSymbolAddress((void**)&attnproj, g_attnproj);
    cudaGetSymbolAddress((void**)&y,        g_y);
    cudaGetSymbolAddress((void**)&yh,       g_yh);
    cudaGetSymbolAddress((void**)&ffhh,     g_ffhh);
    cudaGetSymbolAddress((void**)&ffo,      g_ffo);

    const int gemm_smem = 8 * 1536 * sizeof(unsigned);             // 49152
    const int attn_smem = 3 * 4608 * 4 + 3 * 64 * 4;               // 56064
    cudaFuncSetAttribute(gemm_h<false, false, true, true>,  cudaFuncAttributeMaxDynamicSharedMemorySize, gemm_smem);
    cudaFuncSetAttribute(gemm_h<false, true, false, false>, cudaFuncAttributeMaxDynamicSharedMemorySize, gemm_smem);
    cudaFuncSetAttribute(gemm_h<true, false, true, false>,  cudaFuncAttributeMaxDynamicSharedMemorySize, gemm_smem);
    cudaFuncSetAttribute(attn_h, cudaFuncAttributeMaxDynamicSharedMemorySize, attn_smem);

    // 1) packing
    pack_xh<<<TOK * M_DIM / 1024, 256>>>(x);
    pack_bias<<<(QKV_N + 255) / 256, 256>>>(bq, bk, bv);
    {
        dim3 blk(32, 8);
        pack_qkvT<<<dim3(32, 96), blk>>>(Wq, Wk, Wv);
        packT<<<dim3(32, 32), blk>>>(Wo, Woh, M_DIM, M_DIM);
        packT<<<dim3(32, 64), blk>>>(W1, W1h, M_DIM, FFN_H);
        packT<<<dim3(64, 32), blk>>>(W2, W2h, FFN_H, M_DIM);
    }

    // 2) fused QKV projection (half out + transposed V scatter)
    gemm_h<false, false, true, true><<<dim3(QKV_N / 128, TOK / 128), 256, gemm_smem>>>(
        xh, Wqkvh, bqkv, nullptr, qkvh, vTh, TOK, QKV_N, M_DIM);

    // 3) attention
    attn_h<<<dim3(S_DIM / 128, B_DIM * NHEAD), 256, attn_smem>>>(qkvh, vTh, amask, ctxh);

    // 4) output projection
    gemm_h<false, true, false, false><<<dim3(M_DIM / 128, TOK / 128), 256, gemm_smem>>>(
        ctxh, Woh, bo, attnproj, nullptr, nullptr, TOK, M_DIM, M_DIM);

    // 5) y = LN(attnproj + x)
    ln_kernel<true><<<TOK, 256>>>(attnproj, x, g1, b1, y, yh);

    // 6) ffh = relu(y @ W1 + bias1)
    gemm_h<true, false, true, false><<<dim3(FFN_H / 128, TOK / 128), 256, gemm_smem>>>(
        yh, W1h, bias1, nullptr, ffhh, nullptr, TOK, FFN_H, M_DIM);

    // 7) ffo = ffh @ W2 + bias2
    gemm_h<false, true, false, false><<<dim3(M_DIM / 128, TOK / 128), 256, gemm_smem>>>(
        ffhh, W2h, bias2, ffo, nullptr, nullptr, TOK, M_DIM, FFN_H);

    // 8) out = LN(y + ffo)
    ln_kernel<false><<<TOK, 256>>>(ffo, y, g2, b2, out, nullptr);
}

// round 16
// speedup vs baseline: 1.6517x; 1.6517x over previous
#include <cuda_runtime.h>
#include <cuda_fp16.h>
#include <stdint.h>
#include <math.h>

#define B_DIM 2
#define S_DIM 2048
#define M_DIM 1024
#define NHEAD 16
#define HDIM 64
#define FFN_H 2048
#define TOK (B_DIM * S_DIM)          // 4096
#define QKV_N (3 * M_DIM)            // 3072
#define NEGV -1e9f

// ------------------------- scratch (static device) -------------------------
__device__ __half g_xh[TOK * M_DIM];
__device__ __half g_Wqkvh[QKV_N * M_DIM];
__device__ __half g_Woh[M_DIM * M_DIM];
__device__ __half g_W1h[FFN_H * M_DIM];
__device__ __half g_W2h[M_DIM * FFN_H];
__device__ float  g_bqkv[QKV_N];
__device__ __half g_qkvh[TOK * QKV_N];
__device__ __half g_vTh[B_DIM * M_DIM * S_DIM];
__device__ __half g_ctxh[TOK * M_DIM];
__device__ float  g_attnproj[TOK * M_DIM];
__device__ float  g_y[TOK * M_DIM];
__device__ __half g_yh[TOK * M_DIM];
__device__ __half g_ffhh[TOK * FFN_H];
__device__ float  g_ffo[TOK * M_DIM];

// ------------------------- helpers ------------------------------------
__device__ __forceinline__ void mma16(float* c, const unsigned* a, const unsigned* b) {
    asm volatile(
        "mma.sync.aligned.m16n8k16.row.col.f32.f16.f16.f32 "
        "{%0,%1,%2,%3},{%4,%5,%6,%7},{%8,%9},{%0,%1,%2,%3};"
        : "+f"(c[0]), "+f"(c[1]), "+f"(c[2]), "+f"(c[3])
        : "r"(a[0]), "r"(a[1]), "r"(a[2]), "r"(a[3]), "r"(b[0]), "r"(b[1]));
}
__device__ __forceinline__ void cp16(uint32_t dst, const void* src) {
    asm volatile("cp.async.cg.shared.global [%0], [%1], 16;\n" :: "r"(dst), "l"(src));
}
#define CP_COMMIT() asm volatile("cp.async.commit_group;\n" ::: "memory")
#define CP_WAIT(n)  asm volatile("cp.async.wait_group %0;\n" :: "n"(n) : "memory")
__device__ __forceinline__ unsigned h2u(__half2 h) { return *(unsigned*)&h; }

// ------------------------- pack kernels -------------------------------------
__global__ void pack_xh(const float* __restrict__ x) {
    int i = (blockIdx.x * blockDim.x + threadIdx.x) * 4;
    float4 v = *(const float4*)&x[i];
    __half2* d = (__half2*)&g_xh[i];
    d[0] = __floats2half2_rn(v.x, v.y);
    d[1] = __floats2half2_rn(v.z, v.w);
}
__global__ void pack_bias(const float* __restrict__ bq, const float* __restrict__ bk,
                          const float* __restrict__ bv) {
    int idx = blockIdx.x * blockDim.x + threadIdx.x;
    if (idx < QKV_N) {
        int which = idx / M_DIM, hd = idx % M_DIM;
        const float* bb = (which == 0) ? bq : (which == 1) ? bk : bv;
        g_bqkv[idx] = bb[hd];
    }
}
__global__ void pack_qkvT(const float* __restrict__ Wq, const float* __restrict__ Wk,
                          const float* __restrict__ Wv) {
    __shared__ float t[32][33];
    const int k0 = blockIdx.x * 32, n0 = blockIdx.y * 32;
    const int which = n0 >> 10, hd0 = n0 & 1023, h = hd0 >> 6, d0 = hd0 & 63;
    const float* W = (which == 0) ? Wq : (which == 1) ? Wk : Wv;
    const int tx = threadIdx.x, ty = threadIdx.y;
#pragma unroll
    for (int yy = ty; yy < 32; yy += 8)
        t[yy][tx] = W[((size_t)(h << 10) + k0 + yy) * 64 + d0 + tx];
    __syncthreads();
#pragma unroll
    for (int yy = ty; yy < 32; yy += 8)
        g_Wqkvh[(size_t)(n0 + yy) * M_DIM + k0 + tx] = __float2half_rn(t[tx][yy]);
}
__global__ void packT(const float* __restrict__ src, __half* __restrict__ dst,
                      int K, int N) {
    __shared__ float t[32][33];
    const int k0 = blockIdx.x * 32, n0 = blockIdx.y * 32;
    const int tx = threadIdx.x, ty = threadIdx.y;
#pragma unroll
    for (int yy = ty; yy < 32; yy += 8)
        t[yy][tx] = src[(size_t)(k0 + yy) * N + n0 + tx];
    __syncthreads();
#pragma unroll
    for (int yy = ty; yy < 32; yy += 8)
        dst[(size_t)(n0 + yy) * K + k0 + tx] = __float2half_rn(t[tx][yy]);
}

// ------------------------- fp16 tensor-core GEMM (cp.async 4-stage) --------
// C = A[M,K] @ Bt[N,K]^T + bias, fp32 accum. Optional ReLU.
// 128 threads = 4 warps (2x2), warp tile 64x64 on a 128x128 CTA tile:
// A and B fragment redundancy drop to 2x each (smem-crossbar was the
// binding pipe at 64x32 warp tiles).
template <bool RELU, bool WF, bool WH, bool VT>
__global__ __launch_bounds__(128, 2)
void gemm_h(const __half* __restrict__ A, const __half* __restrict__ Bt,
            const float* __restrict__ bias, float* __restrict__ Cf,
            __half* __restrict__ Ch, __half* __restrict__ vT,
            int M, int N, int K) {
    extern __shared__ unsigned smw[];
    const int tid = threadIdx.x, lane = tid & 31, w = tid >> 5;
    const int wm = w >> 1, wn = w & 1;
    const int g = lane >> 2, tg = lane & 3;
    const int row0 = blockIdx.y * 128, col0 = blockIdx.x * 128;

    const int r = tid >> 1, sel = tid & 1;       // rows r, r+64
    const __half* Agp = A + (size_t)(row0 + r) * K + sel * 8;
    const __half* Bgp = Bt + (size_t)(col0 + r) * K + sel * 8;

    uint32_t smA = (uint32_t)__cvta_generic_to_shared(smw);
    uint32_t smB = smA + 4 * 1536 * 4;
    const uint32_t dA = smA + (r * 12 + sel * 4) * 4;
    const uint32_t dB = smB + (r * 12 + sel * 4) * 4;
    const uint32_t dOff = 64 * 12 * 4;           // +64 rows

    float acc[4][8][4];
#pragma unroll
    for (int i = 0; i < 4; i++)
#pragma unroll
        for (int j = 0; j < 8; j++)
#pragma unroll
            for (int q = 0; q < 4; q++) acc[i][j][q] = 0.f;

    const int T = K >> 4;

    auto issue = [&](int s, int k0) {
        cp16(dA + s * 6144, Agp + k0);
        cp16(dA + s * 6144 + dOff, Agp + (size_t)64 * K + k0);
        cp16(dB + s * 6144, Bgp + k0);
        cp16(dB + s * 6144 + dOff, Bgp + (size_t)64 * K + k0);
        CP_COMMIT();
    };

    issue(0, 0);
    issue(1, 16);
    issue(2, 32);

    for (int t = 0; t < T; t++) {
        CP_WAIT(2);
        __syncthreads();

        const int cur = t & 3;
        const unsigned* as = smw + cur * 1536;
        const unsigned* bs = smw + 4 * 1536 + cur * 1536;

        unsigned af[4][4];
#pragma unroll
        for (int mi = 0; mi < 4; mi++) {
            const unsigned* ap = as + (wm * 64 + mi * 16) * 12;
            af[mi][0] = ap[g * 12 + tg];
            af[mi][1] = ap[(g + 8) * 12 + tg];
            af[mi][2] = ap[g * 12 + tg + 4];
            af[mi][3] = ap[(g + 8) * 12 + tg + 4];
        }
#pragma unroll
        for (int ni = 0; ni < 8; ni++) {
            const unsigned* bw = bs + (wn * 64 + ni * 8 + g) * 12;
            unsigned bf[2];
            bf[0] = bw[tg];
            bf[1] = bw[tg + 4];
#pragma unroll
            for (int mi = 0; mi < 4; mi++) mma16(acc[mi][ni], af[mi], bf);
        }

        if (t + 3 < T) issue((t + 3) & 3, (t + 3) * 16);
        else           CP_COMMIT();
    }

    // epilogue
#pragma unroll
    for (int mi = 0; mi < 4; mi++) {
        const int rw = row0 + wm * 64 + mi * 16 + g;
#pragma unroll
        for (int ni = 0; ni < 8; ni++) {
            const int c = col0 + wn * 64 + ni * 8 + 2 * tg;
            const float b0 = bias[c], b1 = bias[c + 1];
            float v0 = acc[mi][ni][0] + b0, v1 = acc[mi][ni][1] + b1;
            float v2 = acc[mi][ni][2] + b0, v3 = acc[mi][ni][3] + b1;
            if (RELU) {
                v0 = fmaxf(v0, 0.f); v1 = fmaxf(v1, 0.f);
                v2 = fmaxf(v2, 0.f); v3 = fmaxf(v3, 0.f);
            }
            if (WF) {
                *(float2*)&Cf[(size_t)rw * N + c] = make_float2(v0, v1);
                *(float2*)&Cf[(size_t)(rw + 8) * N + c] = make_float2(v2, v3);
            }
            if (WH) {
                *(__half2*)&Ch[(size_t)rw * N + c] = __floats2half2_rn(v0, v1);
                *(__half2*)&Ch[(size_t)(rw + 8) * N + c] = __floats2half2_rn(v2, v3);
            }
            if (VT) {
                if (c >= 2 * M_DIM) {
                    const int bb2 = rw >> 11, ss = rw & 2047;
                    const int hd = c - 2 * M_DIM;
                    __half* p0 = vT + (size_t)(bb2 * M_DIM + hd) * S_DIM + ss;
                    p0[0] = __float2half_rn(v0);
                    p0[8] = __float2half_rn(v2);
                    p0[S_DIM]     = __float2half_rn(v1);
                    p0[S_DIM + 8] = __float2half_rn(v3);
                }
            }
        }
    }
}

// ------------------------- fp16 flash attention (r12, known good) ----------
__global__ __launch_bounds__(256, 2)
void attn_h(const __half* __restrict__ qkvh, const __half* __restrict__ vTh,
            const int* __restrict__ mask, __half* __restrict__ ctx) {
    extern __shared__ unsigned smu[];
    float* Msf = (float*)(smu + 3 * 4608);      // [3][64]

    const int tid = threadIdx.x, lane = tid & 31, w = tid >> 5;
    const int g = lane >> 2, tg = lane & 3;
    const int bh = blockIdx.y, b = bh >> 4, h = bh & 15;
    const int qw = blockIdx.x * 128 + w * 16;

    uint32_t smb = (uint32_t)__cvta_generic_to_shared(smu);

    // Q fragments (half2 words), pre-scaled by 0.125
    unsigned qf[4][4];
    {
        const __half2 sc = __float2half2_rn(0.125f);
        const __half* qb = qkvh + (size_t)(b * S_DIM + qw + g) * QKV_N + h * HDIM;
        const __half* qb8 = qb + (size_t)8 * QKV_N;
#pragma unroll
        for (int fk = 0; fk < 4; fk++) {
            qf[fk][0] = h2u(__hmul2(*(const __half2*)&qb [fk * 16 + 2 * tg], sc));
            qf[fk][1] = h2u(__hmul2(*(const __half2*)&qb8[fk * 16 + 2 * tg], sc));
            qf[fk][2] = h2u(__hmul2(*(const __half2*)&qb [fk * 16 + 8 + 2 * tg], sc));
            qf[fk][3] = h2u(__hmul2(*(const __half2*)&qb8[fk * 16 + 8 + 2 * tg], sc));
        }
    }

    float of[8][4];
#pragma unroll
    for (int i = 0; i < 8; i++) { of[i][0] = of[i][1] = of[i][2] = of[i][3] = 0.f; }
    float m0 = -INFINITY, m1 = -INFINITY, l0 = 0.f, l1 = 0.f;

    const int key = tid >> 2, c0 = tid & 3;
    auto issue = [&](int s, int kt) {
        const __half* srcK = qkvh + (size_t)(b * S_DIM + kt + key) * QKV_N + M_DIM + h * HDIM;
        const __half* srcV = vTh + (size_t)(b * M_DIM + h * HDIM + key) * S_DIM + kt;
        const uint32_t dK = smb + (s * 4608 + key * 36) * 4;
        const uint32_t dV = dK + 2304 * 4;
#pragma unroll
        for (int i = 0; i < 2; i++) {
            const int c = c0 + i * 4;
            cp16(dK + c * 16, srcK + c * 8);
            cp16(dV + c * 16, srcV + c * 8);
        }
        CP_COMMIT();
        if (tid < 64) Msf[s * 64 + tid] = mask[b * S_DIM + kt + tid] ? 0.f : NEGV;
    };

    const int T = S_DIM / 64;
    issue(0, 0);
    issue(1, 64);

    for (int t = 0; t < T; t++) {
        CP_WAIT(1);
        __syncthreads();

        const int cur = t % 3;
        const unsigned* Kw = smu + cur * 4608;
        const unsigned* Vw = Kw + 2304;
        const float* Ms = Msf + cur * 64;

        // S = Q * K^T  (16 x 64 per warp)
        float s[8][4];
#pragma unroll
        for (int fn = 0; fn < 8; fn++) { s[fn][0] = s[fn][1] = s[fn][2] = s[fn][3] = 0.f; }
#pragma unroll
        for (int fk = 0; fk < 4; fk++) {
#pragma unroll
            for (int fn = 0; fn < 8; fn++) {
                const unsigned* kw = Kw + (fn * 8 + g) * 36 + fk * 8;
                unsigned bf[2];
                bf[0] = kw[tg];
                bf[1] = kw[tg + 4];
                mma16(s[fn], qf[fk], bf);
            }
        }

        // mask + online softmax (rows g, g+8)
        float mx0 = -INFINITY, mx1 = -INFINITY;
#pragma unroll
        for (int fn = 0; fn < 8; fn++) {
            const float mk0 = Ms[fn * 8 + 2 * tg], mk1 = Ms[fn * 8 + 2 * tg + 1];
            s[fn][0] += mk0; s[fn][1] += mk1;
            s[fn][2] += mk0; s[fn][3] += mk1;
            mx0 = fmaxf(mx0, fmaxf(s[fn][0], s[fn][1]));
            mx1 = fmaxf(mx1, fmaxf(s[fn][2], s[fn][3]));
        }
        mx0 = fmaxf(mx0, __shfl_xor_sync(0xffffffffu, mx0, 1));
        mx0 = fmaxf(mx0, __shfl_xor_sync(0xffffffffu, mx0, 2));
        mx1 = fmaxf(mx1, __shfl_xor_sync(0xffffffffu, mx1, 1));
        mx1 = fmaxf(mx1, __shfl_xor_sync(0xffffffffu, mx1, 2));
        const float nm0 = fmaxf(m0, mx0), nm1 = fmaxf(m1, mx1);
        const float a0 = __expf(m0 - nm0), a1 = __expf(m1 - nm1);
        m0 = nm0; m1 = nm1;
        l0 *= a0; l1 *= a1;
#pragma unroll
        for (int fn = 0; fn < 8; fn++) {
            of[fn][0] *= a0; of[fn][1] *= a0;
            of[fn][2] *= a1; of[fn][3] *= a1;
            s[fn][0] = __expf(s[fn][0] - m0);
            s[fn][1] = __expf(s[fn][1] - m0);
            s[fn][2] = __expf(s[fn][2] - m1);
            s[fn][3] = __expf(s[fn][3] - m1);
            l0 += s[fn][0] + s[fn][1];
            l1 += s[fn][2] + s[fn][3];
        }

        // P fragments directly from registers
        unsigned pf[4][4];
#pragma unroll
        for (int j = 0; j < 4; j++) {
            pf[j][0] = h2u(__floats2half2_rn(s[2 * j][0],     s[2 * j][1]));
            pf[j][1] = h2u(__floats2half2_rn(s[2 * j][2],     s[2 * j][3]));
            pf[j][2] = h2u(__floats2half2_rn(s[2 * j + 1][0], s[2 * j + 1][1]));
            pf[j][3] = h2u(__floats2half2_rn(s[2 * j + 1][2], s[2 * j + 1][3]));
        }

        // O += P * V
#pragma unroll
        for (int j = 0; j < 4; j++) {
#pragma unroll
            for (int fn = 0; fn < 8; fn++) {
                const unsigned* vw = Vw + (fn * 8 + g) * 36 + j * 8;
                unsigned bf[2];
                bf[0] = vw[tg];
                bf[1] = vw[tg + 4];
                mma16(of[fn], pf[j], bf);
            }
        }

        if (t + 2 < T) issue((t + 2) % 3, (t + 2) * 64);
        else           CP_COMMIT();
    }

    l0 += __shfl_xor_sync(0xffffffffu, l0, 1);
    l0 += __shfl_xor_sync(0xffffffffu, l0, 2);
    l1 += __shfl_xor_sync(0xffffffffu, l1, 1);
    l1 += __shfl_xor_sync(0xffffffffu, l1, 2);

    const float i0 = 1.f / fmaxf(l0, 1e-30f), i1 = 1.f / fmaxf(l1, 1e-30f);
    __half* cb = ctx + (size_t)(b * S_DIM + qw) * M_DIM + h * HDIM;
#pragma unroll
    for (int fn = 0; fn < 8; fn++) {
        *(__half2*)&cb[(size_t)g * M_DIM + fn * 8 + 2 * tg] =
            __floats2half2_rn(of[fn][0] * i0, of[fn][1] * i0);
        *(__half2*)&cb[(size_t)(g + 8) * M_DIM + fn * 8 + 2 * tg] =
            __floats2half2_rn(of[fn][2] * i1, of[fn][3] * i1);
    }
}

// ------------------------- residual + layernorm ----------------------------
template <bool WH>
__global__ __launch_bounds__(256)
void ln_kernel(const float* __restrict__ A, const float* __restrict__ R,
               const float* __restrict__ g, const float* __restrict__ be,
               float* __restrict__ out, __half* __restrict__ outh) {
    __shared__ float red[8];
    __shared__ float bcast;
    const int row = blockIdx.x;
    const int tid = threadIdx.x;

    float4 a = ((const float4*)(A + (size_t)row * M_DIM))[tid];
    float4 r = ((const float4*)(R + (size_t)row * M_DIM))[tid];
    float v0 = a.x + r.x, v1 = a.y + r.y, v2 = a.z + r.z, v3 = a.w + r.w;

    float s = v0 + v1 + v2 + v3;
#pragma unroll
    for (int off = 16; off; off >>= 1) s += __shfl_xor_sync(0xffffffffu, s, off);
    if ((tid & 31) == 0) red[tid >> 5] = s;
    __syncthreads();
    if (tid == 0) {
        float t = 0.f;
#pragma unroll
        for (int i = 0; i < 8; i++) t += red[i];
        bcast = t * (1.f / M_DIM);
    }
    __syncthreads();
    const float mu = bcast;

    float d0 = v0 - mu, d1 = v1 - mu, d2 = v2 - mu, d3 = v3 - mu;
    float s2 = d0 * d0 + d1 * d1 + d2 * d2 + d3 * d3;
#pragma unroll
    for (int off = 16; off; off >>= 1) s2 += __shfl_xor_sync(0xffffffffu, s2, off);
    __syncthreads();
    if ((tid & 31) == 0) red[tid >> 5] = s2;
    __syncthreads();
    if (tid == 0) {
        float t = 0.f;
#pragma unroll
        for (int i = 0; i < 8; i++) t += red[i];
        bcast = rsqrtf(t * (1.f / M_DIM) + 1e-5f);
    }
    __syncthreads();
    const float rstd = bcast;

    float4 gg = ((const float4*)g)[tid];
    float4 bb = ((const float4*)be)[tid];
    float4 o;
    o.x = d0 * rstd * gg.x + bb.x;
    o.y = d1 * rstd * gg.y + bb.y;
    o.z = d2 * rstd * gg.z + bb.z;
    o.w = d3 * rstd * gg.w + bb.w;
    ((float4*)(out + (size_t)row * M_DIM))[tid] = o;
    if (WH) {
        __half2* hd = (__half2*)&outh[(size_t)row * M_DIM + tid * 4];
        hd[0] = __floats2half2_rn(o.x, o.y);
        hd[1] = __floats2half2_rn(o.z, o.w);
    }
}

// ---------------------------------------------------------------------------
extern "C" void kernel_launch(void* const* d_in, const int* in_sizes, int n_in,
                              void* d_out, int out_size) {
    const float* x     = (const float*)d_in[0];
    const int*   amask = (const int*)  d_in[1];
    const float* Wq    = (const float*)d_in[2];
    const float* bq    = (const float*)d_in[3];
    const float* Wk    = (const float*)d_in[4];
    const float* bk    = (const float*)d_in[5];
    const float* Wv    = (const float*)d_in[6];
    const float* bv    = (const float*)d_in[7];
    const float* Wo    = (const float*)d_in[8];
    const float* bo    = (const float*)d_in[9];
    const float* g1    = (const float*)d_in[10];
    const float* b1    = (const float*)d_in[11];
    const float* W1    = (const float*)d_in[12];
    const float* bias1 = (const float*)d_in[13];
    const float* W2    = (const float*)d_in[14];
    const float* bias2 = (const float*)d_in[15];
    const float* g2    = (const float*)d_in[16];
    const float* b2    = (const float*)d_in[17];
    float* out = (float*)d_out;

    __half *xh, *Wqkvh, *Woh, *W1h, *W2h, *qkvh, *vTh, *ctxh, *yh, *ffhh;
    float *bqkv, *attnproj, *y, *ffo;
    cudaGetSymbolAddress((void**)&xh,       g_xh);
    cudaGetSymbolAddress((void**)&Wqkvh,    g_Wqkvh);
    cudaGetSymbolAddress((void**)&Woh,      g_Woh);
    cudaGetSymbolAddress((void**)&W1h,      g_W1h);
    cudaGetSymbolAddress((void**)&W2h,      g_W2h);
    cudaGetSymbolAddress((void**)&bqkv,     g_bqkv);
    cudaGetSymbolAddress((void**)&qkvh,     g_qkvh);
    cudaGetSymbolAddress((void**)&vTh,      g_vTh);
    cudaGetSymbolAddress((void**)&ctxh,     g_ctxh);
    cudaGetSymbolAddress((void**)&attnproj, g_attnproj);
    cudaGetSymbolAddress((void**)&y,        g_y);
    cudaGetSymbolAddress((void**)&yh,       g_yh);
    cudaGetSymbolAddress((void**)&ffhh,     g_ffhh);
    cudaGetSymbolAddress((void**)&ffo,      g_ffo);

    const int gemm_smem = 8 * 1536 * sizeof(unsigned);             // 49152
    const int attn_smem = 3 * 4608 * 4 + 3 * 64 * 4;               // 56064
    cudaFuncSetAttribute(gemm_h<false, false, true, true>,  cudaFuncAttributeMaxDynamicSharedMemorySize, gemm_smem);
    cudaFuncSetAttribute(gemm_h<false, true, false, false>, cudaFuncAttributeMaxDynamicSharedMemorySize, gemm_smem);
    cudaFuncSetAttribute(gemm_h<true, false, true, false>,  cudaFuncAttributeMaxDynamicSharedMemorySize, gemm_smem);
    cudaFuncSetAttribute(attn_h, cudaFuncAttributeMaxDynamicSharedMemorySize, attn_smem);

    // 1) packing
    pack_xh<<<TOK * M_DIM / 1024, 256>>>(x);
    pack_bias<<<(QKV_N + 255) / 256, 256>>>(bq, bk, bv);
    {
        dim3 blk(32, 8);
        pack_qkvT<<<dim3(32, 96), blk>>>(Wq, Wk, Wv);
        packT<<<dim3(32, 32), blk>>>(Wo, Woh, M_DIM, M_DIM);
        packT<<<dim3(32, 64), blk>>>(W1, W1h, M_DIM, FFN_H);
        packT<<<dim3(64, 32), blk>>>(W2, W2h, FFN_H, M_DIM);
    }

    // 2) fused QKV projection (half out + transposed V scatter)
    gemm_h<false, false, true, true><<<dim3(QKV_N / 128, TOK / 128), 128, gemm_smem>>>(
        xh, Wqkvh, bqkv, nullptr, qkvh, vTh, TOK, QKV_N, M_DIM);

    // 3) attention
    attn_h<<<dim3(S_DIM / 128, B_DIM * NHEAD), 256, attn_smem>>>(qkvh, vTh, amask, ctxh);

    // 4) output projection
    gemm_h<false, true, false, false><<<dim3(M_DIM / 128, TOK / 128), 128, gemm_smem>>>(
        ctxh, Woh, bo, attnproj, nullptr, nullptr, TOK, M_DIM, M_DIM);

    // 5) y = LN(attnproj + x)
    ln_kernel<true><<<TOK, 256>>>(attnproj, x, g1, b1, y, yh);

    // 6) ffh = relu(y @ W1 + bias1)
    gemm_h<true, false, true, false><<<dim3(FFN_H / 128, TOK / 128), 128, gemm_smem>>>(
        yh, W1h, bias1, nullptr, ffhh, nullptr, TOK, FFN_H, M_DIM);

    // 7) ffo = ffh @ W2 + bias2
    gemm_h<false, true, false, false><<<dim3(M_DIM / 128, TOK / 128), 128, gemm_smem>>>(
        ffhh, W2h, bias2, ffo, nullptr, nullptr, TOK, M_DIM, FFN_H);

    // 8) out = LN(y + ffo)
    ln_kernel<false><<<TOK, 256>>>(ffo, y, g2, b2, out, nullptr);
}